// round 6
// baseline (speedup 1.0000x reference)
#include <cuda_runtime.h>
#include <cuda_bf16.h>
#include <cstdint>
#include <math.h>

// ---------------- problem constants ----------------
#define Bq   2
#define Cc   128
#define Hf   256
#define Wf   256
#define Nf   (Hf*Wf)      // 65536
#define Hh   128
#define Wh   128
#define Nh2  (Hh*Wh)      // 16384
#define NHh  8
#define HD   16

#define HB   ((size_t)Bq*Cc*Nh2)

// ---------------- device scratch ----------------
__device__ float g_qkv [(size_t)Bq*3*Cc*Nf];
__device__ float g_qkvd[(size_t)Bq*3*Cc*Nf];
__device__ float g_hbuf[10*((size_t)Bq*Cc*Nh2)];
__device__ float g_masks[(size_t)Bq*5*Cc*Nh2];
__device__ float g_qcat [(size_t)Bq*2*Cc*Nh2];
__device__ float g_qfull[(size_t)Bq*Cc*Nf];
__device__ float g_gram [Bq*NHh*288];
__device__ float g_weff [Bq*Cc*Cc];

__device__ __forceinline__ float sigm(float v) { return 1.f/(1.f+__expf(-v)); }

__device__ __forceinline__ uint32_t smem_u32(const void* p) {
    uint32_t a;
    asm("{ .reg .u64 t; cvta.to.shared.u64 t, %1; cvt.u32.u64 %0, t; }" : "=r"(a) : "l"(p));
    return a;
}

// =====================================================================
// tf32 / mma / cp.async helpers
// =====================================================================
__device__ __forceinline__ uint32_t f2tf32(float f) {
    uint32_t r;
    asm("cvt.rna.tf32.f32 %0, %1;" : "=r"(r) : "f"(f));
    return r;
}
__device__ __forceinline__ void mma_tf32(float c[4], const uint32_t a[4], const uint32_t b[2]) {
    asm volatile(
        "mma.sync.aligned.m16n8k8.row.col.f32.tf32.tf32.f32 "
        "{%0,%1,%2,%3}, {%4,%5,%6,%7}, {%8,%9}, {%0,%1,%2,%3};"
        : "+f"(c[0]), "+f"(c[1]), "+f"(c[2]), "+f"(c[3])
        : "r"(a[0]), "r"(a[1]), "r"(a[2]), "r"(a[3]), "r"(b[0]), "r"(b[1]));
}
#define CP_ASYNC16(dst, src) \
    asm volatile("cp.async.cg.shared.global [%0], [%1], 16;" :: "r"(dst), "l"(src))
#define CP_COMMIT() asm volatile("cp.async.commit_group;" ::: "memory")
#define CP_WAIT0()  asm volatile("cp.async.wait_group 0;" ::: "memory")
#define CP_WAIT1()  asm volatile("cp.async.wait_group 1;" ::: "memory")

// =====================================================================
// conv1x1 as tf32 tensor-core GEMM, cp.async double-buffered B staging.
//   out[o,p] = epi( sum_c W[o,c] * in[c,p] + bias[o] )
// Block 256 thr (8 warps 4x2). BM=128(o), BN=128(p), BK=32.
// EPI: 0=bias, 1=sigmoid, 2=residual+mask
// =====================================================================
#define A_STR 36
#define B_STR 132
#define BBUF  (32*B_STR)                   // u32 per B buffer
#define CONV_SMEM ((128*A_STR + 2*BBUF)*4) // bytes = 52224

template<int EPI>
__global__ void __launch_bounds__(256) conv1x1_mma(
    const float* __restrict__ in, const float* __restrict__ w,
    const float* __restrict__ bias, float* __restrict__ out,
    const float* __restrict__ mask,
    int Cin, int P,
    size_t inBS, size_t outBS, size_t wBS, size_t maskBS)
{
    extern __shared__ uint32_t sdyn[];
    uint32_t* As = sdyn;                 // tf32 weights tile
    uint32_t* Bs = sdyn + 128*A_STR;     // 2 buffers: raw f32 -> tf32 in place
    const uint32_t bs_addr = smem_u32(Bs);

    const int b = blockIdx.z;
    in  += (size_t)b * inBS;
    out += (size_t)b * outBS;
    w   += (size_t)b * wBS;
    if (EPI == 2) mask += (size_t)b * maskBS;

    const int p0 = blockIdx.x * 128;
    const int o0 = blockIdx.y * 128;

    const int t = threadIdx.x;
    const int lane = t & 31;
    const int wrp  = t >> 5;
    const int wm   = wrp & 3;
    const int wn   = wrp >> 2;
    const int gid  = lane >> 2;
    const int tig  = lane & 3;

    float acc[2][8][4];
#pragma unroll
    for (int i = 0; i < 2; i++)
#pragma unroll
        for (int j = 0; j < 8; j++)
#pragma unroll
            for (int r = 0; r < 4; r++) acc[i][j][r] = 0.f;

    const int nStages = Cin >> 5;

    // precomputed slot coords for B staging (4 chunks/thread)
    const int bc  = t >> 5;        // base row 0..7 (+8 per chunk)
    const int bp4 = t & 31;        // 16B col chunk

    // preamble: issue B stage 0 into buf 0
    {
        const float* ib = in + p0;
#pragma unroll
        for (int i = 0; i < 4; i++) {
            const int c = bc + i * 8;
            CP_ASYNC16(bs_addr + (uint32_t)(c * B_STR + bp4 * 4) * 4,
                       ib + (size_t)c * P + bp4 * 4);
        }
        CP_COMMIT();
    }

    for (int stage = 0; stage < nStages; stage++) {
        const int cbase = stage << 5;
        const int buf   = stage & 1;

        // ---- stage A (sync): weights -> tf32 -> As
        {
            const float* wb = w + (size_t)o0 * Cin + cbase;
#pragma unroll
            for (int i = 0; i < 4; i++) {
                const int slot = t + i * 256;
                const int o  = slot >> 3;
                const int c4 = slot & 7;
                const float4 v = *(const float4*)(wb + (size_t)o * Cin + c4 * 4);
                uint4 u;
                u.x = f2tf32(v.x); u.y = f2tf32(v.y);
                u.z = f2tf32(v.z); u.w = f2tf32(v.w);
                *(uint4*)(As + o * A_STR + c4 * 4) = u;
            }
        }
        // ---- prefetch B stage+1 into other buf, then wait for B stage
        if (stage + 1 < nStages) {
            const float* ib = in + (size_t)((stage + 1) << 5) * P + p0;
            const uint32_t dstb = bs_addr + (uint32_t)((buf ^ 1) * BBUF) * 4;
#pragma unroll
            for (int i = 0; i < 4; i++) {
                const int c = bc + i * 8;
                CP_ASYNC16(dstb + (uint32_t)(c * B_STR + bp4 * 4) * 4,
                           ib + (size_t)c * P + bp4 * 4);
            }
            CP_COMMIT();
            CP_WAIT1();
        } else {
            CP_WAIT0();
        }
        __syncthreads();

        // ---- in-place f32 -> tf32 on B[buf] (each thread owns its chunks)
        {
            uint32_t* bb = Bs + buf * BBUF;
#pragma unroll
            for (int i = 0; i < 4; i++) {
                const int c = bc + i * 8;
                uint32_t* p4p = bb + c * B_STR + bp4 * 4;
                const float4 v = *(const float4*)p4p;
                uint4 u;
                u.x = f2tf32(v.x); u.y = f2tf32(v.y);
                u.z = f2tf32(v.z); u.w = f2tf32(v.w);
                *(uint4*)p4p = u;
            }
        }
        __syncthreads();

        // ---- compute
        const uint32_t* bb = Bs + buf * BBUF;
#pragma unroll
        for (int k0 = 0; k0 < 32; k0 += 8) {
            uint32_t af[2][4];
#pragma unroll
            for (int tm = 0; tm < 2; tm++) {
                const int rb = wm * 32 + tm * 16;
                af[tm][0] = As[(rb + gid    ) * A_STR + k0 + tig    ];
                af[tm][1] = As[(rb + gid + 8) * A_STR + k0 + tig    ];
                af[tm][2] = As[(rb + gid    ) * A_STR + k0 + tig + 4];
                af[tm][3] = As[(rb + gid + 8) * A_STR + k0 + tig + 4];
            }
#pragma unroll
            for (int tn = 0; tn < 8; tn++) {
                uint32_t bf[2];
                const int col = wn * 64 + tn * 8 + gid;
                bf[0] = bb[(k0 + tig    ) * B_STR + col];
                bf[1] = bb[(k0 + tig + 4) * B_STR + col];
#pragma unroll
                for (int tm = 0; tm < 2; tm++)
                    mma_tf32(acc[tm][tn], af[tm], bf);
            }
        }
        __syncthreads();
    }

    // ---- epilogue
#pragma unroll
    for (int tm = 0; tm < 2; tm++) {
        const int oA = o0 + wm * 32 + tm * 16 + gid;
        const int oB = oA + 8;
        const float bvA = __ldg(bias + oA);
        const float bvB = __ldg(bias + oB);
#pragma unroll
        for (int tn = 0; tn < 8; tn++) {
            const int p = p0 + wn * 64 + tn * 8 + tig * 2;
            float v0 = acc[tm][tn][0] + bvA;
            float v1 = acc[tm][tn][1] + bvA;
            float v2 = acc[tm][tn][2] + bvB;
            float v3 = acc[tm][tn][3] + bvB;
            if (EPI == 1) {
                v0 = sigm(v0); v1 = sigm(v1); v2 = sigm(v2); v3 = sigm(v3);
            }
            if (EPI == 2) {
                const float2 iA = *(const float2*)(in + (size_t)oA * P + p);
                const float2 iB = *(const float2*)(in + (size_t)oB * P + p);
                const float2 mA = *(const float2*)(mask + (size_t)oA * P + p);
                const float2 mB = *(const float2*)(mask + (size_t)oB * P + p);
                v0 = iA.x + v0 * mA.x; v1 = iA.y + v1 * mA.y;
                v2 = iB.x + v2 * mB.x; v3 = iB.y + v3 * mB.y;
            }
            *(float2*)(out + (size_t)oA * P + p) = make_float2(v0, v1);
            *(float2*)(out + (size_t)oB * P + p) = make_float2(v2, v3);
        }
    }
}

// =====================================================================
// smem-tiled depthwise 3x3 on k,v channels (full res)
// =====================================================================
__global__ void __launch_bounds__(256) dwconv3_s(
    const float* __restrict__ in, const float* __restrict__ wk,
    const float* __restrict__ wv, float* __restrict__ out)
{
    __shared__ float sm[10][132];
    const int zc2 = blockIdx.z;              // b*2C + ch2
    const int b   = zc2 / (2*Cc);
    const int ch2 = zc2 % (2*Cc);
    const int cm  = ch2 % Cc;
    const float* ws = (ch2 < Cc) ? wk : wv;
    float wgt[9];
#pragma unroll
    for (int i=0;i<9;i++) wgt[i] = __ldg(ws + cm*9 + i);

    const size_t off = ((size_t)b*3*Cc + Cc + ch2)*Nf;
    const float* ip = in  + off;
    float*       op = out + off;

    const int X0 = blockIdx.x*128;
    const int Y0 = blockIdx.y*8;
    const int t  = threadIdx.y*32 + threadIdx.x;

    for (int idx = t; idx < 10*130; idx += 256) {
        const int r = idx / 130, c = idx % 130;
        const int gy = Y0 - 1 + r, gx = X0 - 1 + c;
        sm[r][c] = ((unsigned)gy < (unsigned)Hf && (unsigned)gx < (unsigned)Wf)
                   ? __ldg(ip + (size_t)gy*Wf + gx) : 0.f;
    }
    __syncthreads();

    const int ty = threadIdx.y;
    const int x0 = threadIdx.x*4;
    float o[4] = {0.f,0.f,0.f,0.f};
#pragma unroll
    for (int ky=0; ky<3; ky++) {
        float row[6];
#pragma unroll
        for (int j=0; j<6; j++) row[j] = sm[ty+ky][x0+j];
#pragma unroll
        for (int kx=0; kx<3; kx++) {
            const float wv_ = wgt[ky*3+kx];
#pragma unroll
            for (int j=0; j<4; j++) o[j] = fmaf(row[j+kx], wv_, o[j]);
        }
    }
    *(float4*)(op + (size_t)(Y0+ty)*Wf + X0 + x0) = make_float4(o[0],o[1],o[2],o[3]);
}

// =====================================================================
// fused: depthwise 3x3 on q + Haar DWT, smem-tiled.
// Half-res out tile 32x8 -> full-res in tile 18 x 66.
// =====================================================================
__global__ void __launch_bounds__(256) dwconv_dwt_k(
    const float* __restrict__ in, const float* __restrict__ wq,
    float* __restrict__ ll, float* __restrict__ lh,
    float* __restrict__ hl, float* __restrict__ hh)
{
    __shared__ float sm[18][68];
    const int zc = blockIdx.z;               // b*C + ch
    const int b = zc / Cc, ch = zc % Cc;
    float wgt[9];
#pragma unroll
    for (int i=0;i<9;i++) wgt[i] = __ldg(wq + ch*9 + i);

    const float* ip = in + ((size_t)b*3*Cc + ch)*Nf;
    const size_t ho = (size_t)zc*Nh2;

    const int Xh0 = blockIdx.x*32;           // half-res tile origin
    const int Yh0 = blockIdx.y*8;
    const int t   = threadIdx.y*32 + threadIdx.x;

    // full-res region rows [2*Yh0-1, 2*Yh0+16], cols [2*Xh0-1, 2*Xh0+64]
    for (int idx = t; idx < 18*66; idx += 256) {
        const int r = idx / 66, c = idx % 66;
        const int gy = 2*Yh0 - 1 + r, gx = 2*Xh0 - 1 + c;
        sm[r][c] = ((unsigned)gy < (unsigned)Hf && (unsigned)gx < (unsigned)Wf)
                   ? __ldg(ip + (size_t)gy*Wf + gx) : 0.f;
    }
    __syncthreads();

    const int xh = threadIdx.x;              // 0..31
    const int yh = threadIdx.y;              // 0..7
    // conv output quad at full-res (2*yh, 2*xh) local: sm row base 2*yh, col base 2*xh
    float o[2][2];
#pragma unroll
    for (int qy=0; qy<2; qy++)
#pragma unroll
        for (int qx=0; qx<2; qx++) {
            float s = 0.f;
#pragma unroll
            for (int ky=0; ky<3; ky++)
#pragma unroll
                for (int kx=0; kx<3; kx++)
                    s = fmaf(sm[2*yh+qy+ky][2*xh+qx+kx], wgt[ky*3+kx], s);
            o[qy][qx] = s;
        }
    const float a = o[0][0], bb = o[0][1], c = o[1][0], d = o[1][1];
    const size_t p = ho + (size_t)(Yh0+yh)*Wh + Xh0 + xh;
    ll[p] = (a+bb+c+d)*0.5f;
    lh[p] = (a+bb-c-d)*0.5f;
    hl[p] = (a-bb+c-d)*0.5f;
    hh[p] = (a-bb-c+d)*0.5f;
}

// =====================================================================
// smem-tiled single-stage gated conv
// =====================================================================
template<int KH,int KW>
__global__ void __launch_bounds__(256) gated_s(
    const float* __restrict__ in, const float* __restrict__ w,
    float* __restrict__ out)
{
    constexpr int HALO_Y = KH/2, HALO_X = KW/2;
    constexpr int TR = 8 + KH - 1;
    constexpr int TC = 128 + KW - 1;
    __shared__ float sm[TR][TC];
    __shared__ float wsm[2][KH*KW];

    const int zc = blockIdx.z;
    const int ch = zc % Cc;
    const int t  = threadIdx.y*32 + threadIdx.x;
    if (t < 2*KH*KW) {
        const int br = t / (KH*KW), i = t % (KH*KW);
        wsm[br][i] = __ldg(w + (size_t)br*Cc*KH*KW + (size_t)ch*KH*KW + i);
    }

    const float* ip = in + (size_t)zc*Nh2;
    const int Y0 = blockIdx.y*8;

    for (int idx = t; idx < TR*TC; idx += 256) {
        const int r = idx / TC, c = idx % TC;
        const int gy = Y0 - HALO_Y + r, gx = c - HALO_X;
        sm[r][c] = ((unsigned)gy < (unsigned)Hh && (unsigned)gx < (unsigned)Wh)
                   ? __ldg(ip + (size_t)gy*Wh + gx) : 0.f;
    }
    __syncthreads();

    const int ty = threadIdx.y;
    const int x0 = threadIdx.x*4;
    float s0[4] = {0,0,0,0}, s1[4] = {0,0,0,0};
#pragma unroll
    for (int ky=0; ky<KH; ky++) {
        float row[KW+3];
#pragma unroll
        for (int j=0; j<KW+3; j++) row[j] = sm[ty+ky][x0+j];
#pragma unroll
        for (int kx=0; kx<KW; kx++) {
            const float a0 = wsm[0][ky*KW+kx], a1 = wsm[1][ky*KW+kx];
#pragma unroll
            for (int j=0; j<4; j++) {
                s0[j] = fmaf(row[j+kx], a0, s0[j]);
                s1[j] = fmaf(row[j+kx], a1, s1[j]);
            }
        }
    }
    float4 o;
    o.x = s0[0]*sigm(s1[0]); o.y = s0[1]*sigm(s1[1]);
    o.z = s0[2]*sigm(s1[2]); o.w = s0[3]*sigm(s1[3]);
    *(float4*)(out + (size_t)zc*Nh2 + (size_t)(Y0+ty)*Wh + x0) = o;
}

// =====================================================================
// fused dual 2-stage gated chains; min-blocks hint for occupancy
// =====================================================================
__global__ void __launch_bounds__(256, 5) gated2_dual_k(
    const float* __restrict__ in,
    const float* __restrict__ wA, const float* __restrict__ wB,
    float* __restrict__ outA, float* __restrict__ outB)
{
    __shared__ float sm[12][132];
    __shared__ float midA[10][132];
    __shared__ float midB[10][132];
    __shared__ float wsm[8][9];

    const int zc = blockIdx.z;
    const int ch = zc % Cc;
    const int t  = threadIdx.y*32 + threadIdx.x;

    if (t < 72) {
        const int set = t / 9, i = t % 9;
        const float* base = (set < 4) ? wA : wB;
        const int s4 = set & 3;
        wsm[set][i] = __ldg(base + (size_t)s4*Cc*9 + (size_t)ch*9 + i);
    }

    const float* ip = in + (size_t)zc*Nh2;
    const int Y0 = blockIdx.y*8;

    for (int idx = t; idx < 12*132; idx += 256) {
        const int r = idx / 132, c = idx % 132;
        const int gy = Y0 - 2 + r, gx = c - 2;
        sm[r][c] = ((unsigned)gy < (unsigned)Hh && (unsigned)gx < (unsigned)Wh)
                   ? __ldg(ip + (size_t)gy*Wh + gx) : 0.f;
    }
    __syncthreads();

    for (int idx = t; idx < 10*130; idx += 256) {
        const int r = idx / 130, c = idx % 130;
        const int gy = Y0 - 1 + r, gx = c - 1;
        float a0=0, a1=0, b0=0, b1=0;
        if ((unsigned)gy < (unsigned)Hh && (unsigned)gx < (unsigned)Wh) {
#pragma unroll
            for (int ky=0; ky<3; ky++)
#pragma unroll
                for (int kx=0; kx<3; kx++) {
                    const float v = sm[r+ky][c+kx];
                    const int i = ky*3+kx;
                    a0 = fmaf(v, wsm[0][i], a0);
                    a1 = fmaf(v, wsm[1][i], a1);
                    b0 = fmaf(v, wsm[4][i], b0);
                    b1 = fmaf(v, wsm[5][i], b1);
                }
        }
        midA[r][c] = a0 * sigm(a1);
        midB[r][c] = b0 * sigm(b1);
    }
    __syncthreads();

    const int ty = threadIdx.y;
    const int x0 = threadIdx.x*4;
    float sA0[4]={0,0,0,0}, sA1[4]={0,0,0,0}, sB0[4]={0,0,0,0}, sB1[4]={0,0,0,0};
#pragma unroll
    for (int ky=0; ky<3; ky++) {
        float rA[6], rB[6];
#pragma unroll
        for (int j=0; j<6; j++) { rA[j] = midA[ty+ky][x0+j]; rB[j] = midB[ty+ky][x0+j]; }
#pragma unroll
        for (int kx=0; kx<3; kx++) {
            const int i = ky*3+kx;
            const float a2_0 = wsm[2][i], a2_1 = wsm[3][i];
            const float b2_0 = wsm[6][i], b2_1 = wsm[7][i];
#pragma unroll
            for (int j=0; j<4; j++) {
                sA0[j] = fmaf(rA[j+kx], a2_0, sA0[j]);
                sA1[j] = fmaf(rA[j+kx], a2_1, sA1[j]);
                sB0[j] = fmaf(rB[j+kx], b2_0, sB0[j]);
                sB1[j] = fmaf(rB[j+kx], b2_1, sB1[j]);
            }
        }
    }
    const size_t op = (size_t)zc*Nh2 + (size_t)(Y0+ty)*Wh + x0;
    float4 oA, oB;
    oA.x = sA0[0]*sigm(sA1[0]); oA.y = sA0[1]*sigm(sA1[1]);
    oA.z = sA0[2]*sigm(sA1[2]); oA.w = sA0[3]*sigm(sA1[3]);
    oB.x = sB0[0]*sigm(sB1[0]); oB.y = sB0[1]*sigm(sB1[1]);
    oB.z = sB0[2]*sigm(sB1[2]); oB.w = sB0[3]*sigm(sB1[3]);
    *(float4*)(outA + op) = oA;
    *(float4*)(outB + op) = oB;
}

// =====================================================================
// inverse DWT with masks, 2 px/thread
// =====================================================================
__global__ void __launch_bounds__(256) idwt_k(
    const float* __restrict__ ll, const float* __restrict__ lh,
    const float* __restrict__ hl, const float* __restrict__ hh,
    const float* __restrict__ masks, float* __restrict__ out)
{
    const int zc = blockIdx.z;
    const int b = zc / Cc, ch = zc % Cc;
    const size_t hp = (size_t)zc*Nh2;
    const float* mb = masks + (size_t)b*5*Cc*Nh2;

    const int x0 = (blockIdx.x*32 + threadIdx.x)*2;
    const int y  = blockIdx.y*8  + threadIdx.y;
    const size_t p = (size_t)y*Wh + x0;

    const float2 vll = *(const float2*)(ll+hp+p);
    float2 vlh = *(const float2*)(lh+hp+p);
    float2 vhl = *(const float2*)(hl+hp+p);
    float2 vhh = *(const float2*)(hh+hp+p);
    const float2 m1 = *(const float2*)(mb + (size_t)(  Cc+ch)*Nh2 + p);
    const float2 m2 = *(const float2*)(mb + (size_t)(2*Cc+ch)*Nh2 + p);
    const float2 m3 = *(const float2*)(mb + (size_t)(3*Cc+ch)*Nh2 + p);
    vlh.x *= m1.x; vlh.y *= m1.y;
    vhl.x *= m2.x; vhl.y *= m2.y;
    vhh.x *= m3.x; vhh.y *= m3.y;

    float* op = out + (size_t)zc*Nf;
    float4 t0, t1;
    t0.x = (vll.x+vlh.x+vhl.x+vhh.x)*0.5f;
    t0.y = (vll.x+vlh.x-vhl.x-vhh.x)*0.5f;
    t0.z = (vll.y+vlh.y+vhl.y+vhh.y)*0.5f;
    t0.w = (vll.y+vlh.y-vhl.y-vhh.y)*0.5f;
    t1.x = (vll.x-vlh.x+vhl.x-vhh.x)*0.5f;
    t1.y = (vll.x-vlh.x-vhl.x+vhh.x)*0.5f;
    t1.z = (vll.y-vlh.y+vhl.y-vhh.y)*0.5f;
    t1.w = (vll.y-vlh.y-vhl.y+vhh.y)*0.5f;
    *(float4*)(op + (size_t)(2*y)*Wf   + 2*x0) = t0;
    *(float4*)(op + (size_t)(2*y+1)*Wf + 2*x0) = t1;
}

// =====================================================================
// gram pass
// =====================================================================
#define GRAM_TILES 8
__global__ void __launch_bounds__(256) gram_k(const float* __restrict__ q,
                                              const float* __restrict__ kall,
                                              float* __restrict__ gram)
{
    const int h = blockIdx.y, b = blockIdx.z;
    const float* qb = q    + (size_t)b*Cc*Nf            + (size_t)h*HD*Nf;
    const float* kb = kall + (size_t)b*3*Cc*Nf + (size_t)Cc*Nf + (size_t)h*HD*Nf;

    __shared__ float qs[16][132];
    __shared__ float ks[16][132];

    const int t = threadIdx.x;
    const int i = t >> 4, j = t & 15;
    float accS = 0.f, accQ = 0.f, accK = 0.f;

    const int n0base = blockIdx.x * (GRAM_TILES*128);
    for (int tile=0; tile<GRAM_TILES; tile++) {
        const int n0 = n0base + tile*128;
#pragma unroll
        for (int e=0; e<2; e++) {
            const int idx = t + e*256;
            const int r = idx >> 5, c4 = idx & 31;
            const float4 vq = *(const float4*)(qb + (size_t)r*Nf + n0 + c4*4);
            const float4 vk = *(const float4*)(kb + (size_t)r*Nf + n0 + c4*4);
            *(float4*)&qs[r][c4*4] = vq;
            *(float4*)&ks[r][c4*4] = vk;
        }
        __syncthreads();
#pragma unroll 8
        for (int nn=0; nn<128; nn++) {
            const float qv = qs[i][nn];
            const float kv = ks[j][nn];
            accS = fmaf(qv, kv, accS);
            if (j == 0) accQ = fmaf(qv, qv, accQ);
            if (i == 0) accK = fmaf(kv, kv, accK);
        }
        __syncthreads();
    }
    float* gp = gram + (size_t)(b*NHh + h)*288;
    atomicAdd(gp + i*16 + j, accS);
    if (j == 0) atomicAdd(gp + 256 + i, accQ);
    if (i == 0) atomicAdd(gp + 272 + j, accK);
}

// =====================================================================
// softmax + fold w_out
// =====================================================================
__global__ void attw_k(const float* __restrict__ gram,
                       const float* __restrict__ temp,
                       const float* __restrict__ wout,
                       float* __restrict__ weff)
{
    const int b = blockIdx.x;
    __shared__ float att[NHh][16][16];
    const int t = threadIdx.x;
    const float* gb = gram + (size_t)b*NHh*288;

    if (t < 128) {
        const int h = t >> 4, i = t & 15;
        const float* gp = gb + h*288;
        const float nq = fmaxf(sqrtf(gp[256+i]), 1e-12f);
        const float tv = temp[h];
        float logit[16];
        float mx = -1e30f;
#pragma unroll
        for (int j=0;j<16;j++) {
            const float nk = fmaxf(sqrtf(gp[272+j]), 1e-12f);
            const float l = gp[i*16+j] / (nq*nk) * tv;
            logit[j] = l;
            mx = fmaxf(mx, l);
        }
        float se = 0.f;
#pragma unroll
        for (int j=0;j<16;j++) { const float e = __expf(logit[j]-mx); logit[j]=e; se+=e; }
        const float inv = 1.f/se;
#pragma unroll
        for (int j=0;j<16;j++) att[h][i][j] = logit[j]*inv;
    }
    __syncthreads();

    float* wb = weff + (size_t)b*Cc*Cc;
    for (int idx = t; idx < Cc*Cc; idx += 256) {
        const int o = idx >> 7, cp = idx & 127;
        const int h = cp >> 4, j = cp & 15;
        float s = 0.f;
#pragma unroll
        for (int i=0;i<16;i++)
            s = fmaf(wout[(size_t)o*Cc + h*16 + i], att[h][i][j], s);
        wb[idx] = s;
    }
}

// =====================================================================
// host launch
// =====================================================================
extern "C" void kernel_launch(void* const* d_in, const int* in_sizes, int n_in,
                              void* d_out, int out_size)
{
    const float* x      = (const float*)d_in[0];
    const float* prior  = (const float*)d_in[1];
    const float* w_lin  = (const float*)d_in[2];
    const float* b_lin  = (const float*)d_in[3];
    const float* w_qd   = (const float*)d_in[4];
    const float* w_kd   = (const float*)d_in[5];
    const float* w_vd   = (const float*)d_in[6];
    const float* gw_llr = (const float*)d_in[7];
    const float* gw_llh = (const float*)d_in[8];
    const float* gw_lh  = (const float*)d_in[9];
    const float* gw_hl  = (const float*)d_in[10];
    const float* gw_hh  = (const float*)d_in[11];
    const float* w_prior= (const float*)d_in[12];
    const float* b_prior= (const float*)d_in[13];
    const float* w_pw1  = (const float*)d_in[14];
    const float* b_pw1  = (const float*)d_in[15];
    const float* w_pw2  = (const float*)d_in[16];
    const float* b_pw2  = (const float*)d_in[17];
    const float* w_cat  = (const float*)d_in[18];
    const float* b_cat  = (const float*)d_in[19];
    const float* temper = (const float*)d_in[20];
    const float* w_out  = (const float*)d_in[21];
    const float* b_out  = (const float*)d_in[22];

    float *qkv, *qkvd, *hbuf, *masks, *qcat, *qfull, *gram, *weff;
    cudaGetSymbolAddress((void**)&qkv,   g_qkv);
    cudaGetSymbolAddress((void**)&qkvd,  g_qkvd);
    cudaGetSymbolAddress((void**)&hbuf,  g_hbuf);
    cudaGetSymbolAddress((void**)&masks, g_masks);
    cudaGetSymbolAddress((void**)&qcat,  g_qcat);
    cudaGetSymbolAddress((void**)&qfull, g_qfull);
    cudaGetSymbolAddress((void**)&gram,  g_gram);
    cudaGetSymbolAddress((void**)&weff,  g_weff);

    // dynamic smem limit for the GEMM kernels (52224 B) — idempotent host call
    cudaFuncSetAttribute(conv1x1_mma<0>, cudaFuncAttributeMaxDynamicSharedMemorySize, CONV_SMEM);
    cudaFuncSetAttribute(conv1x1_mma<1>, cudaFuncAttributeMaxDynamicSharedMemorySize, CONV_SMEM);
    cudaFuncSetAttribute(conv1x1_mma<2>, cudaFuncAttributeMaxDynamicSharedMemorySize, CONV_SMEM);

    float* ll   = hbuf + 0*HB;
    float* lh   = hbuf + 1*HB;
    float* hl   = hbuf + 2*HB;
    float* hh   = hbuf + 3*HB;
    float* llrg = hbuf + 5*HB;
    float* llhg = hbuf + 6*HB;
    float* lhg  = hbuf + 7*HB;
    float* hlg  = hbuf + 8*HB;
    float* hhg  = hbuf + 9*HB;

    const size_t fullBS = (size_t)Cc*Nf;
    const size_t qkvBS  = (size_t)3*Cc*Nf;
    const size_t halfBS = (size_t)Cc*Nh2;
    const size_t mBS    = (size_t)5*Cc*Nh2;
    const size_t catBS  = (size_t)2*Cc*Nh2;

    // 1. qkv = conv1x1(x, w_lin) + b_lin
    conv1x1_mma<0><<<dim3(Nf/128, 3, Bq), 256, CONV_SMEM>>>(
        x, w_lin, b_lin, qkv, nullptr, Cc, Nf, fullBS, qkvBS, 0, 0);

    // 2a. depthwise 3x3 on k,v (smem-tiled)
    dwconv3_s<<<dim3(Wf/128, Hf/8, Bq*2*Cc), dim3(32,8)>>>(qkv, w_kd, w_vd, qkvd);
    // 2b. fused depthwise 3x3 on q + Haar DWT (smem-tiled)
    dwconv_dwt_k<<<dim3(Wh/32, Hh/8, Bq*Cc), dim3(32,8)>>>(qkv, w_qd, ll, lh, hl, hh);

    // 3. gated chains
    dim3 gg(1, Hh/8, Bq*Cc), bg(32,8);
    gated2_dual_k<<<gg, bg>>>(ll, gw_llr, gw_llh, llrg, llhg);
    gated_s<3,5><<<gg, bg>>>(lh, gw_lh, lhg);
    gated_s<5,3><<<gg, bg>>>(hl, gw_hl, hlg);
    gated_s<3,3><<<gg, bg>>>(hh, gw_hh, hhg);

    // 4. masks = sigmoid(conv1x1(prior, w_prior))
    conv1x1_mma<1><<<dim3(Nh2/128, 5, Bq), 256, CONV_SMEM>>>(
        prior, w_prior, b_prior, masks, nullptr, Cc, Nh2, halfBS, mBS, 0, 0);

    // 5. pw residual-mask blocks -> qcat
    conv1x1_mma<2><<<dim3(Nh2/128, 1, Bq), 256, CONV_SMEM>>>(
        llrg, w_pw1, b_pw1, qcat, masks, Cc, Nh2, halfBS, catBS, 0, mBS);
    conv1x1_mma<2><<<dim3(Nh2/128, 1, Bq), 256, CONV_SMEM>>>(
        llhg, w_pw2, b_pw2, qcat + (size_t)Cc*Nh2, masks + (size_t)4*Cc*Nh2, Cc, Nh2,
        halfBS, catBS, 0, mBS);

    // 6. q_ll = conv1x1(cat, w_cat) + b_cat
    conv1x1_mma<0><<<dim3(Nh2/128, 1, Bq), 256, CONV_SMEM>>>(
        qcat, w_cat, b_cat, ll, nullptr, 2*Cc, Nh2, catBS, halfBS, 0, 0);

    // 7. inverse DWT with masks
    idwt_k<<<dim3(Wh/64, Hh/8, Bq*Cc), dim3(32,8)>>>(ll, lhg, hlg, hhg, masks, qfull);

    // 8. gram matrices + norms
    cudaMemsetAsync(gram, 0, (size_t)Bq*NHh*288*sizeof(float));
    gram_k<<<dim3(Nf/(GRAM_TILES*128), NHh, Bq), 256>>>(qfull, qkvd, gram);

    // 9. softmax + fold into Weff
    attw_k<<<Bq, 256>>>(gram, temper, w_out, weff);

    // 10. final: out = Weff_b @ v + b_out
    conv1x1_mma<0><<<dim3(Nf/128, 1, Bq), 256, CONV_SMEM>>>(
        qkvd + (size_t)2*Cc*Nf, weff, b_out, (float*)d_out, nullptr, Cc, Nf,
        qkvBS, fullBS, (size_t)Cc*Cc, 0);

    // 11. second output = prior pass-through
    const size_t xel = (size_t)in_sizes[0];
    const size_t pel = (size_t)in_sizes[1];
    if ((size_t)out_size >= xel + pel) {
        cudaMemcpyAsync((float*)d_out + xel, prior, pel*sizeof(float),
                        cudaMemcpyDeviceToDevice);
    }
}

// round 7
// speedup vs baseline: 1.0544x; 1.0544x over previous
#include <cuda_runtime.h>
#include <cuda_bf16.h>
#include <cstdint>
#include <math.h>

// ---------------- problem constants ----------------
#define Bq   2
#define Cc   128
#define Hf   256
#define Wf   256
#define Nf   (Hf*Wf)      // 65536
#define Hh   128
#define Wh   128
#define Nh2  (Hh*Wh)      // 16384
#define NHh  8
#define HD   16

#define HB   ((size_t)Bq*Cc*Nh2)

// ---------------- device scratch ----------------
__device__ float g_qkv [(size_t)Bq*3*Cc*Nf];
__device__ float g_qkvd[(size_t)Bq*3*Cc*Nf];
__device__ float g_hbuf[10*((size_t)Bq*Cc*Nh2)];
__device__ float g_masks[(size_t)Bq*5*Cc*Nh2];
__device__ float g_qcat [(size_t)Bq*2*Cc*Nh2];
__device__ float g_qfull[(size_t)Bq*Cc*Nf];
__device__ float g_gram [Bq*NHh*288];
__device__ float g_weff [Bq*Cc*Cc];

__device__ __forceinline__ float sigm(float v) { return 1.f/(1.f+__expf(-v)); }

// =====================================================================
// tf32 helpers
// =====================================================================
__device__ __forceinline__ uint32_t f2tf32(float f) {
    uint32_t r;
    asm("cvt.rna.tf32.f32 %0, %1;" : "=r"(r) : "f"(f));
    return r;
}
__device__ __forceinline__ void mma_tf32(float c[4], const uint32_t a[4], const uint32_t b[2]) {
    asm volatile(
        "mma.sync.aligned.m16n8k8.row.col.f32.tf32.tf32.f32 "
        "{%0,%1,%2,%3}, {%4,%5,%6,%7}, {%8,%9}, {%0,%1,%2,%3};"
        : "+f"(c[0]), "+f"(c[1]), "+f"(c[2]), "+f"(c[3])
        : "r"(a[0]), "r"(a[1]), "r"(a[2]), "r"(a[3]), "r"(b[0]), "r"(b[1]));
}

// =====================================================================
// conv1x1 as tf32 tensor-core GEMM (R5 version — no cp.async)
// =====================================================================
#define A_STR 36
#define B_STR 132

template<int EPI>
__global__ void __launch_bounds__(256) conv1x1_mma(
    const float* __restrict__ in, const float* __restrict__ w,
    const float* __restrict__ bias, float* __restrict__ out,
    const float* __restrict__ mask,
    int Cin, int P,
    size_t inBS, size_t outBS, size_t wBS, size_t maskBS)
{
    const int b = blockIdx.z;
    in  += (size_t)b * inBS;
    out += (size_t)b * outBS;
    w   += (size_t)b * wBS;
    if (EPI == 2) mask += (size_t)b * maskBS;

    const int p0 = blockIdx.x * 128;
    const int o0 = blockIdx.y * 128;

    __shared__ uint32_t As[128 * A_STR];
    __shared__ uint32_t Bs[32 * B_STR];

    const int t = threadIdx.x;
    const int lane = t & 31;
    const int wrp  = t >> 5;
    const int wm   = wrp & 3;
    const int wn   = wrp >> 2;
    const int gid  = lane >> 2;
    const int tig  = lane & 3;

    float acc[2][8][4];
#pragma unroll
    for (int i = 0; i < 2; i++)
#pragma unroll
        for (int j = 0; j < 8; j++)
#pragma unroll
            for (int r = 0; r < 4; r++) acc[i][j][r] = 0.f;

    const int nStages = Cin >> 5;
    for (int stage = 0; stage < nStages; stage++) {
        const int cbase = stage << 5;
        {
            const float* wb = w + (size_t)o0 * Cin + cbase;
#pragma unroll
            for (int i = 0; i < 4; i++) {
                const int slot = t + i * 256;
                const int o  = slot >> 3;
                const int c4 = slot & 7;
                const float4 v = *(const float4*)(wb + (size_t)o * Cin + c4 * 4);
                uint32_t* dst = As + o * A_STR + c4 * 4;
                dst[0] = f2tf32(v.x); dst[1] = f2tf32(v.y);
                dst[2] = f2tf32(v.z); dst[3] = f2tf32(v.w);
            }
        }
        {
            const float* ib = in + (size_t)cbase * P + p0;
#pragma unroll
            for (int i = 0; i < 4; i++) {
                const int slot = t + i * 256;
                const int c  = slot >> 5;
                const int p4 = slot & 31;
                const float4 v = *(const float4*)(ib + (size_t)c * P + p4 * 4);
                uint32_t* dst = Bs + c * B_STR + p4 * 4;
                dst[0] = f2tf32(v.x); dst[1] = f2tf32(v.y);
                dst[2] = f2tf32(v.z); dst[3] = f2tf32(v.w);
            }
        }
        __syncthreads();

#pragma unroll
        for (int k0 = 0; k0 < 32; k0 += 8) {
            uint32_t af[2][4];
#pragma unroll
            for (int tm = 0; tm < 2; tm++) {
                const int rb = wm * 32 + tm * 16;
                af[tm][0] = As[(rb + gid    ) * A_STR + k0 + tig    ];
                af[tm][1] = As[(rb + gid + 8) * A_STR + k0 + tig    ];
                af[tm][2] = As[(rb + gid    ) * A_STR + k0 + tig + 4];
                af[tm][3] = As[(rb + gid + 8) * A_STR + k0 + tig + 4];
            }
#pragma unroll
            for (int tn = 0; tn < 8; tn++) {
                uint32_t bf[2];
                const int col = wn * 64 + tn * 8 + gid;
                bf[0] = Bs[(k0 + tig    ) * B_STR + col];
                bf[1] = Bs[(k0 + tig + 4) * B_STR + col];
#pragma unroll
                for (int tm = 0; tm < 2; tm++)
                    mma_tf32(acc[tm][tn], af[tm], bf);
            }
        }
        __syncthreads();
    }

#pragma unroll
    for (int tm = 0; tm < 2; tm++) {
        const int oA = o0 + wm * 32 + tm * 16 + gid;
        const int oB = oA + 8;
        const float bvA = __ldg(bias + oA);
        const float bvB = __ldg(bias + oB);
#pragma unroll
        for (int tn = 0; tn < 8; tn++) {
            const int p = p0 + wn * 64 + tn * 8 + tig * 2;
            float v0 = acc[tm][tn][0] + bvA;
            float v1 = acc[tm][tn][1] + bvA;
            float v2 = acc[tm][tn][2] + bvB;
            float v3 = acc[tm][tn][3] + bvB;
            if (EPI == 1) {
                v0 = sigm(v0); v1 = sigm(v1); v2 = sigm(v2); v3 = sigm(v3);
            }
            if (EPI == 2) {
                const float2 iA = *(const float2*)(in + (size_t)oA * P + p);
                const float2 iB = *(const float2*)(in + (size_t)oB * P + p);
                const float2 mA = *(const float2*)(mask + (size_t)oA * P + p);
                const float2 mB = *(const float2*)(mask + (size_t)oB * P + p);
                v0 = iA.x + v0 * mA.x; v1 = iA.y + v1 * mA.y;
                v2 = iB.x + v2 * mB.x; v3 = iB.y + v3 * mB.y;
            }
            *(float2*)(out + (size_t)oA * P + p) = make_float2(v0, v1);
            *(float2*)(out + (size_t)oB * P + p) = make_float2(v2, v3);
        }
    }
}

// =====================================================================
// depthwise 3x3 on k,v channels (R5 direct register version)
// =====================================================================
__global__ void __launch_bounds__(256) dwconv3_k(
    const float* __restrict__ in, const float* __restrict__ wk,
    const float* __restrict__ wv, float* __restrict__ out)
{
    const int zc2 = blockIdx.z;              // b*2C + ch2
    const int b   = zc2 / (2*Cc);
    const int ch2 = zc2 % (2*Cc);
    const int cm  = ch2 % Cc;
    const float* ws = (ch2 < Cc) ? wk : wv;
    float wgt[9];
#pragma unroll
    for (int i=0;i<9;i++) wgt[i] = __ldg(ws + cm*9 + i);

    const size_t off = ((size_t)b*3*Cc + Cc + ch2)*Nf;
    const float* ip = in  + off;
    float*       op = out + off;

    const int x0 = (blockIdx.x*32 + threadIdx.x)*4;
    const int y  = blockIdx.y*8  + threadIdx.y;

    float r[3][6];
#pragma unroll
    for (int dy=0; dy<3; dy++) {
        const int yy = y + dy - 1;
        const bool rv = (unsigned)yy < (unsigned)Hf;
        const float* rp = ip + (size_t)yy*Wf;
#pragma unroll
        for (int j=0; j<6; j++) {
            const int xx = x0 + j - 1;
            r[dy][j] = (rv && (unsigned)xx < (unsigned)Wf) ? __ldg(rp + xx) : 0.f;
        }
    }
    float o[4] = {0.f,0.f,0.f,0.f};
#pragma unroll
    for (int dy=0; dy<3; dy++)
#pragma unroll
        for (int dx=0; dx<3; dx++) {
            const float wv_ = wgt[dy*3+dx];
#pragma unroll
            for (int j=0; j<4; j++) o[j] = fmaf(r[dy][j+dx], wv_, o[j]);
        }
    *(float4*)(op + (size_t)y*Wf + x0) = make_float4(o[0],o[1],o[2],o[3]);
}

// =====================================================================
// fused: depthwise 3x3 on q + Haar DWT (R5 register version)
// =====================================================================
__global__ void __launch_bounds__(256) dwconv_dwt_k(
    const float* __restrict__ in, const float* __restrict__ wq,
    float* __restrict__ ll, float* __restrict__ lh,
    float* __restrict__ hl, float* __restrict__ hh)
{
    const int zc = blockIdx.z;               // b*C + ch
    const int b = zc / Cc, ch = zc % Cc;
    float wgt[9];
#pragma unroll
    for (int i=0;i<9;i++) wgt[i] = __ldg(wq + ch*9 + i);

    const float* ip = in + ((size_t)b*3*Cc + ch)*Nf;
    const size_t ho = (size_t)zc*Nh2;

    const int xh = blockIdx.x*32 + threadIdx.x;
    const int yh = blockIdx.y*8  + threadIdx.y;
    const int x0 = xh*2, y0 = yh*2;

    float r[4][4];
#pragma unroll
    for (int dy=0; dy<4; dy++) {
        const int yy = y0 + dy - 1;
        const bool rv = (unsigned)yy < (unsigned)Hf;
        const float* rp = ip + (size_t)yy*Wf;
#pragma unroll
        for (int dx=0; dx<4; dx++) {
            const int xx = x0 + dx - 1;
            r[dy][dx] = (rv && (unsigned)xx < (unsigned)Wf) ? __ldg(rp + xx) : 0.f;
        }
    }
    float o[2][2];
#pragma unroll
    for (int qy=0; qy<2; qy++)
#pragma unroll
        for (int qx=0; qx<2; qx++) {
            float s = 0.f;
#pragma unroll
            for (int ky=0; ky<3; ky++)
#pragma unroll
                for (int kx=0; kx<3; kx++)
                    s = fmaf(r[qy+ky][qx+kx], wgt[ky*3+kx], s);
            o[qy][qx] = s;
        }
    const float a = o[0][0], bb = o[0][1], c = o[1][0], d = o[1][1];
    const size_t p = ho + (size_t)yh*Wh + xh;
    ll[p] = (a+bb+c+d)*0.5f;
    lh[p] = (a+bb-c-d)*0.5f;
    hl[p] = (a-bb+c-d)*0.5f;
    hh[p] = (a-bb-c+d)*0.5f;
}

// =====================================================================
// smem-tiled single-stage gated conv
// =====================================================================
template<int KH,int KW>
__global__ void __launch_bounds__(256) gated_s(
    const float* __restrict__ in, const float* __restrict__ w,
    float* __restrict__ out)
{
    constexpr int HALO_Y = KH/2, HALO_X = KW/2;
    constexpr int TR = 8 + KH - 1;
    constexpr int TC = 128 + KW - 1;
    __shared__ float sm[TR][TC];
    __shared__ float wsm[2][KH*KW];

    const int zc = blockIdx.z;
    const int ch = zc % Cc;
    const int t  = threadIdx.y*32 + threadIdx.x;
    if (t < 2*KH*KW) {
        const int br = t / (KH*KW), i = t % (KH*KW);
        wsm[br][i] = __ldg(w + (size_t)br*Cc*KH*KW + (size_t)ch*KH*KW + i);
    }

    const float* ip = in + (size_t)zc*Nh2;
    const int Y0 = blockIdx.y*8;

    for (int idx = t; idx < TR*TC; idx += 256) {
        const int r = idx / TC, c = idx % TC;
        const int gy = Y0 - HALO_Y + r, gx = c - HALO_X;
        sm[r][c] = ((unsigned)gy < (unsigned)Hh && (unsigned)gx < (unsigned)Wh)
                   ? __ldg(ip + (size_t)gy*Wh + gx) : 0.f;
    }
    __syncthreads();

    const int ty = threadIdx.y;
    const int x0 = threadIdx.x*4;
    float s0[4] = {0,0,0,0}, s1[4] = {0,0,0,0};
#pragma unroll
    for (int ky=0; ky<KH; ky++) {
        float row[KW+3];
#pragma unroll
        for (int j=0; j<KW+3; j++) row[j] = sm[ty+ky][x0+j];
#pragma unroll
        for (int kx=0; kx<KW; kx++) {
            const float a0 = wsm[0][ky*KW+kx], a1 = wsm[1][ky*KW+kx];
#pragma unroll
            for (int j=0; j<4; j++) {
                s0[j] = fmaf(row[j+kx], a0, s0[j]);
                s1[j] = fmaf(row[j+kx], a1, s1[j]);
            }
        }
    }
    float4 o;
    o.x = s0[0]*sigm(s1[0]); o.y = s0[1]*sigm(s1[1]);
    o.z = s0[2]*sigm(s1[2]); o.w = s0[3]*sigm(s1[3]);
    *(float4*)(out + (size_t)zc*Nh2 + (size_t)(Y0+ty)*Wh + x0) = o;
}

// =====================================================================
// fused dual 2-stage gated chains, occupancy-capped regs
// =====================================================================
__global__ void __launch_bounds__(256, 5) gated2_dual_k(
    const float* __restrict__ in,
    const float* __restrict__ wA, const float* __restrict__ wB,
    float* __restrict__ outA, float* __restrict__ outB)
{
    __shared__ float sm[12][132];
    __shared__ float midA[10][132];
    __shared__ float midB[10][132];
    __shared__ float wsm[8][9];

    const int zc = blockIdx.z;
    const int ch = zc % Cc;
    const int t  = threadIdx.y*32 + threadIdx.x;

    if (t < 72) {
        const int set = t / 9, i = t % 9;
        const float* base = (set < 4) ? wA : wB;
        const int s4 = set & 3;
        wsm[set][i] = __ldg(base + (size_t)s4*Cc*9 + (size_t)ch*9 + i);
    }

    const float* ip = in + (size_t)zc*Nh2;
    const int Y0 = blockIdx.y*8;

    for (int idx = t; idx < 12*132; idx += 256) {
        const int r = idx / 132, c = idx % 132;
        const int gy = Y0 - 2 + r, gx = c - 2;
        sm[r][c] = ((unsigned)gy < (unsigned)Hh && (unsigned)gx < (unsigned)Wh)
                   ? __ldg(ip + (size_t)gy*Wh + gx) : 0.f;
    }
    __syncthreads();

    for (int idx = t; idx < 10*130; idx += 256) {
        const int r = idx / 130, c = idx % 130;
        const int gy = Y0 - 1 + r, gx = c - 1;
        float a0=0, a1=0, b0=0, b1=0;
        if ((unsigned)gy < (unsigned)Hh && (unsigned)gx < (unsigned)Wh) {
#pragma unroll
            for (int ky=0; ky<3; ky++)
#pragma unroll
                for (int kx=0; kx<3; kx++) {
                    const float v = sm[r+ky][c+kx];
                    const int i = ky*3+kx;
                    a0 = fmaf(v, wsm[0][i], a0);
                    a1 = fmaf(v, wsm[1][i], a1);
                    b0 = fmaf(v, wsm[4][i], b0);
                    b1 = fmaf(v, wsm[5][i], b1);
                }
        }
        midA[r][c] = a0 * sigm(a1);
        midB[r][c] = b0 * sigm(b1);
    }
    __syncthreads();

    const int ty = threadIdx.y;
    const int x0 = threadIdx.x*4;
    float sA0[4]={0,0,0,0}, sA1[4]={0,0,0,0}, sB0[4]={0,0,0,0}, sB1[4]={0,0,0,0};
#pragma unroll
    for (int ky=0; ky<3; ky++) {
        float rA[6], rB[6];
#pragma unroll
        for (int j=0; j<6; j++) { rA[j] = midA[ty+ky][x0+j]; rB[j] = midB[ty+ky][x0+j]; }
#pragma unroll
        for (int kx=0; kx<3; kx++) {
            const int i = ky*3+kx;
            const float a2_0 = wsm[2][i], a2_1 = wsm[3][i];
            const float b2_0 = wsm[6][i], b2_1 = wsm[7][i];
#pragma unroll
            for (int j=0; j<4; j++) {
                sA0[j] = fmaf(rA[j+kx], a2_0, sA0[j]);
                sA1[j] = fmaf(rA[j+kx], a2_1, sA1[j]);
                sB0[j] = fmaf(rB[j+kx], b2_0, sB0[j]);
                sB1[j] = fmaf(rB[j+kx], b2_1, sB1[j]);
            }
        }
    }
    const size_t op = (size_t)zc*Nh2 + (size_t)(Y0+ty)*Wh + x0;
    float4 oA, oB;
    oA.x = sA0[0]*sigm(sA1[0]); oA.y = sA0[1]*sigm(sA1[1]);
    oA.z = sA0[2]*sigm(sA1[2]); oA.w = sA0[3]*sigm(sA1[3]);
    oB.x = sB0[0]*sigm(sB1[0]); oB.y = sB0[1]*sigm(sB1[1]);
    oB.z = sB0[2]*sigm(sB1[2]); oB.w = sB0[3]*sigm(sB1[3]);
    *(float4*)(outA + op) = oA;
    *(float4*)(outB + op) = oB;
}

// =====================================================================
// inverse DWT with masks, 2 px/thread
// =====================================================================
__global__ void __launch_bounds__(256) idwt_k(
    const float* __restrict__ ll, const float* __restrict__ lh,
    const float* __restrict__ hl, const float* __restrict__ hh,
    const float* __restrict__ masks, float* __restrict__ out)
{
    const int zc = blockIdx.z;
    const int b = zc / Cc, ch = zc % Cc;
    const size_t hp = (size_t)zc*Nh2;
    const float* mb = masks + (size_t)b*5*Cc*Nh2;

    const int x0 = (blockIdx.x*32 + threadIdx.x)*2;
    const int y  = blockIdx.y*8  + threadIdx.y;
    const size_t p = (size_t)y*Wh + x0;

    const float2 vll = *(const float2*)(ll+hp+p);
    float2 vlh = *(const float2*)(lh+hp+p);
    float2 vhl = *(const float2*)(hl+hp+p);
    float2 vhh = *(const float2*)(hh+hp+p);
    const float2 m1 = *(const float2*)(mb + (size_t)(  Cc+ch)*Nh2 + p);
    const float2 m2 = *(const float2*)(mb + (size_t)(2*Cc+ch)*Nh2 + p);
    const float2 m3 = *(const float2*)(mb + (size_t)(3*Cc+ch)*Nh2 + p);
    vlh.x *= m1.x; vlh.y *= m1.y;
    vhl.x *= m2.x; vhl.y *= m2.y;
    vhh.x *= m3.x; vhh.y *= m3.y;

    float* op = out + (size_t)zc*Nf;
    float4 t0, t1;
    t0.x = (vll.x+vlh.x+vhl.x+vhh.x)*0.5f;
    t0.y = (vll.x+vlh.x-vhl.x-vhh.x)*0.5f;
    t0.z = (vll.y+vlh.y+vhl.y+vhh.y)*0.5f;
    t0.w = (vll.y+vlh.y-vhl.y-vhh.y)*0.5f;
    t1.x = (vll.x-vlh.x+vhl.x-vhh.x)*0.5f;
    t1.y = (vll.x-vlh.x-vhl.x+vhh.x)*0.5f;
    t1.z = (vll.y-vlh.y+vhl.y-vhh.y)*0.5f;
    t1.w = (vll.y-vlh.y-vhl.y+vhh.y)*0.5f;
    *(float4*)(op + (size_t)(2*y)*Wf   + 2*x0) = t0;
    *(float4*)(op + (size_t)(2*y+1)*Wf + 2*x0) = t1;
}

// =====================================================================
// gram pass
// =====================================================================
#define GRAM_TILES 8
__global__ void __launch_bounds__(256) gram_k(const float* __restrict__ q,
                                              const float* __restrict__ kall,
                                              float* __restrict__ gram)
{
    const int h = blockIdx.y, b = blockIdx.z;
    const float* qb = q    + (size_t)b*Cc*Nf            + (size_t)h*HD*Nf;
    const float* kb = kall + (size_t)b*3*Cc*Nf + (size_t)Cc*Nf + (size_t)h*HD*Nf;

    __shared__ float qs[16][132];
    __shared__ float ks[16][132];

    const int t = threadIdx.x;
    const int i = t >> 4, j = t & 15;
    float accS = 0.f, accQ = 0.f, accK = 0.f;

    const int n0base = blockIdx.x * (GRAM_TILES*128);
    for (int tile=0; tile<GRAM_TILES; tile++) {
        const int n0 = n0base + tile*128;
#pragma unroll
        for (int e=0; e<2; e++) {
            const int idx = t + e*256;
            const int r = idx >> 5, c4 = idx & 31;
            const float4 vq = *(const float4*)(qb + (size_t)r*Nf + n0 + c4*4);
            const float4 vk = *(const float4*)(kb + (size_t)r*Nf + n0 + c4*4);
            *(float4*)&qs[r][c4*4] = vq;
            *(float4*)&ks[r][c4*4] = vk;
        }
        __syncthreads();
#pragma unroll 8
        for (int nn=0; nn<128; nn++) {
            const float qv = qs[i][nn];
            const float kv = ks[j][nn];
            accS = fmaf(qv, kv, accS);
            if (j == 0) accQ = fmaf(qv, qv, accQ);
            if (i == 0) accK = fmaf(kv, kv, accK);
        }
        __syncthreads();
    }
    float* gp = gram + (size_t)(b*NHh + h)*288;
    atomicAdd(gp + i*16 + j, accS);
    if (j == 0) atomicAdd(gp + 256 + i, accQ);
    if (i == 0) atomicAdd(gp + 272 + j, accK);
}

// =====================================================================
// softmax + fold w_out
// =====================================================================
__global__ void attw_k(const float* __restrict__ gram,
                       const float* __restrict__ temp,
                       const float* __restrict__ wout,
                       float* __restrict__ weff)
{
    const int b = blockIdx.x;
    __shared__ float att[NHh][16][16];
    const int t = threadIdx.x;
    const float* gb = gram + (size_t)b*NHh*288;

    if (t < 128) {
        const int h = t >> 4, i = t & 15;
        const float* gp = gb + h*288;
        const float nq = fmaxf(sqrtf(gp[256+i]), 1e-12f);
        const float tv = temp[h];
        float logit[16];
        float mx = -1e30f;
#pragma unroll
        for (int j=0;j<16;j++) {
            const float nk = fmaxf(sqrtf(gp[272+j]), 1e-12f);
            const float l = gp[i*16+j] / (nq*nk) * tv;
            logit[j] = l;
            mx = fmaxf(mx, l);
        }
        float se = 0.f;
#pragma unroll
        for (int j=0;j<16;j++) { const float e = __expf(logit[j]-mx); logit[j]=e; se+=e; }
        const float inv = 1.f/se;
#pragma unroll
        for (int j=0;j<16;j++) att[h][i][j] = logit[j]*inv;
    }
    __syncthreads();

    float* wb = weff + (size_t)b*Cc*Cc;
    for (int idx = t; idx < Cc*Cc; idx += 256) {
        const int o = idx >> 7, cp = idx & 127;
        const int h = cp >> 4, j = cp & 15;
        float s = 0.f;
#pragma unroll
        for (int i=0;i<16;i++)
            s = fmaf(wout[(size_t)o*Cc + h*16 + i], att[h][i][j], s);
        wb[idx] = s;
    }
}

// =====================================================================
// host launch — event-forked multi-stream overlap (graph-capture legal)
// =====================================================================
extern "C" void kernel_launch(void* const* d_in, const int* in_sizes, int n_in,
                              void* d_out, int out_size)
{
    const float* x      = (const float*)d_in[0];
    const float* prior  = (const float*)d_in[1];
    const float* w_lin  = (const float*)d_in[2];
    const float* b_lin  = (const float*)d_in[3];
    const float* w_qd   = (const float*)d_in[4];
    const float* w_kd   = (const float*)d_in[5];
    const float* w_vd   = (const float*)d_in[6];
    const float* gw_llr = (const float*)d_in[7];
    const float* gw_llh = (const float*)d_in[8];
    const float* gw_lh  = (const float*)d_in[9];
    const float* gw_hl  = (const float*)d_in[10];
    const float* gw_hh  = (const float*)d_in[11];
    const float* w_prior= (const float*)d_in[12];
    const float* b_prior= (const float*)d_in[13];
    const float* w_pw1  = (const float*)d_in[14];
    const float* b_pw1  = (const float*)d_in[15];
    const float* w_pw2  = (const float*)d_in[16];
    const float* b_pw2  = (const float*)d_in[17];
    const float* w_cat  = (const float*)d_in[18];
    const float* b_cat  = (const float*)d_in[19];
    const float* temper = (const float*)d_in[20];
    const float* w_out  = (const float*)d_in[21];
    const float* b_out  = (const float*)d_in[22];

    float *qkv, *qkvd, *hbuf, *masks, *qcat, *qfull, *gram, *weff;
    cudaGetSymbolAddress((void**)&qkv,   g_qkv);
    cudaGetSymbolAddress((void**)&qkvd,  g_qkvd);
    cudaGetSymbolAddress((void**)&hbuf,  g_hbuf);
    cudaGetSymbolAddress((void**)&masks, g_masks);
    cudaGetSymbolAddress((void**)&qcat,  g_qcat);
    cudaGetSymbolAddress((void**)&qfull, g_qfull);
    cudaGetSymbolAddress((void**)&gram,  g_gram);
    cudaGetSymbolAddress((void**)&weff,  g_weff);

    // streams/events created once (setup, not per-call work; no device mem)
    static cudaStream_t s1 = nullptr, s2 = nullptr;
    static cudaEvent_t eStart = nullptr, eQkv = nullptr, eKV = nullptr, eM = nullptr;
    if (s1 == nullptr) {
        cudaStreamCreateWithFlags(&s1, cudaStreamNonBlocking);
        cudaStreamCreateWithFlags(&s2, cudaStreamNonBlocking);
        cudaEventCreateWithFlags(&eStart, cudaEventDisableTiming);
        cudaEventCreateWithFlags(&eQkv,   cudaEventDisableTiming);
        cudaEventCreateWithFlags(&eKV,    cudaEventDisableTiming);
        cudaEventCreateWithFlags(&eM,     cudaEventDisableTiming);
    }

    float* ll   = hbuf + 0*HB;
    float* lh   = hbuf + 1*HB;
    float* hl   = hbuf + 2*HB;
    float* hh   = hbuf + 3*HB;
    float* llrg = hbuf + 5*HB;
    float* llhg = hbuf + 6*HB;
    float* lhg  = hbuf + 7*HB;
    float* hlg  = hbuf + 8*HB;
    float* hhg  = hbuf + 9*HB;

    const size_t fullBS = (size_t)Cc*Nf;
    const size_t qkvBS  = (size_t)3*Cc*Nf;
    const size_t halfBS = (size_t)Cc*Nh2;
    const size_t mBS    = (size_t)5*Cc*Nh2;
    const size_t catBS  = (size_t)2*Cc*Nh2;

    // fork side streams from the capture (default) stream
    cudaEventRecord(eStart, 0);
    cudaStreamWaitEvent(s2, eStart, 0);

    // s2: masks = sigmoid(conv1x1(prior)) — independent of qkv
    conv1x1_mma<1><<<dim3(Nh2/128, 5, Bq), 256, 0, s2>>>(
        prior, w_prior, b_prior, masks, nullptr, Cc, Nh2, halfBS, mBS, 0, 0);
    cudaEventRecord(eM, s2);

    // 0: qkv = conv1x1(x, w_lin) + b_lin
    conv1x1_mma<0><<<dim3(Nf/128, 3, Bq), 256>>>(
        x, w_lin, b_lin, qkv, nullptr, Cc, Nf, fullBS, qkvBS, 0, 0);
    cudaEventRecord(eQkv, 0);

    // s1: depthwise 3x3 on k,v + gram memset (big, overlaps q-branch)
    cudaStreamWaitEvent(s1, eQkv, 0);
    dwconv3_k<<<dim3(Wf/128, Hf/8, Bq*2*Cc), dim3(32,8), 0, s1>>>(qkv, w_kd, w_vd, qkvd);
    cudaMemsetAsync(gram, 0, (size_t)Bq*NHh*288*sizeof(float), s1);
    cudaEventRecord(eKV, s1);

    // 0: q branch — fused dwconv+DWT, gated chains
    dwconv_dwt_k<<<dim3(Wh/32, Hh/8, Bq*Cc), dim3(32,8)>>>(qkv, w_qd, ll, lh, hl, hh);
    dim3 gg(1, Hh/8, Bq*Cc), bg(32,8);
    gated2_dual_k<<<gg, bg>>>(ll, gw_llr, gw_llh, llrg, llhg);
    gated_s<3,5><<<gg, bg>>>(lh, gw_lh, lhg);
    gated_s<5,3><<<gg, bg>>>(hl, gw_hl, hlg);
    gated_s<3,3><<<gg, bg>>>(hh, gw_hh, hhg);

    // join masks before pw/idwt
    cudaStreamWaitEvent(0, eM, 0);

    // 0: pw residual-mask blocks -> qcat
    conv1x1_mma<2><<<dim3(Nh2/128, 1, Bq), 256>>>(
        llrg, w_pw1, b_pw1, qcat, masks, Cc, Nh2, halfBS, catBS, 0, mBS);
    conv1x1_mma<2><<<dim3(Nh2/128, 1, Bq), 256>>>(
        llhg, w_pw2, b_pw2, qcat + (size_t)Cc*Nh2, masks + (size_t)4*Cc*Nh2, Cc, Nh2,
        halfBS, catBS, 0, mBS);

    // 0: q_ll = conv1x1(cat, w_cat) + b_cat
    conv1x1_mma<0><<<dim3(Nh2/128, 1, Bq), 256>>>(
        qcat, w_cat, b_cat, ll, nullptr, 2*Cc, Nh2, catBS, halfBS, 0, 0);

    // 0: inverse DWT with masks
    idwt_k<<<dim3(Wh/64, Hh/8, Bq*Cc), dim3(32,8)>>>(ll, lhg, hlg, hhg, masks, qfull);

    // join k,v branch before gram / final conv
    cudaStreamWaitEvent(0, eKV, 0);

    // 0: gram + softmax-fold + final conv
    gram_k<<<dim3(Nf/(GRAM_TILES*128), NHh, Bq), 256>>>(qfull, qkvd, gram);
    attw_k<<<Bq, 256>>>(gram, temper, w_out, weff);
    conv1x1_mma<0><<<dim3(Nf/128, 1, Bq), 256>>>(
        qkvd + (size_t)2*Cc*Nf, weff, b_out, (float*)d_out, nullptr, Cc, Nf,
        qkvBS, fullBS, (size_t)Cc*Cc, 0);

    // 0: second output = prior pass-through
    const size_t xel = (size_t)in_sizes[0];
    const size_t pel = (size_t)in_sizes[1];
    if ((size_t)out_size >= xel + pel) {
        cudaMemcpyAsync((float*)d_out + xel, prior, pel*sizeof(float),
                        cudaMemcpyDeviceToDevice);
    }
}